// round 3
// baseline (speedup 1.0000x reference)
#include <cuda_runtime.h>

// DeepFilter with register sliding window over time.
// spec:  (B=8, 2, T=4096, F=481) f32
// coefs: (B=8, 10, T=4096, 256) f32  (c[0..4]=real taps, c[5..9]=imag taps)

#define NUM_FREQS 256
#define FRAME_SIZE 5
#define T_DIM 4096
#define F_TOTAL 481
#define B_DIM 8

#define T_STRIP 16
#define STRIPS_PER_BLK 2
#define T_BLK (T_STRIP * STRIPS_PER_BLK)   // 32 t-values per block
#define NPASS (F_TOTAL - NUM_FREQS)        // 225 passthrough bins

__global__ __launch_bounds__(128, 4)
void deepfilter_kernel(const float* __restrict__ spec,
                       const float* __restrict__ coefs,
                       float* __restrict__ out)
{
    const int fx = threadIdx.x;            // 0..63 -> 4 freq bins each
    const int f0 = fx * 4;
    const int b  = blockIdx.y;
    const int t0 = (blockIdx.x * STRIPS_PER_BLK + threadIdx.y) * T_STRIP;

    const long spec_ch = (long)T_DIM * F_TOTAL;
    const long spec_b  = 2 * spec_ch;
    const long coef_c  = (long)T_DIM * NUM_FREQS;
    const long coef_b  = 2 * FRAME_SIZE * coef_c;

    const float* sp = spec + (long)b * spec_b;
    float*       op = out  + (long)b * spec_b;

    // ---- filtered region: sliding 5-tap window in registers ----
    float wr[FRAME_SIZE][4], wi[FRAME_SIZE][4];

    // preload rows t0-4 .. t0-1 into taps 0..3
    #pragma unroll
    for (int j = 0; j < FRAME_SIZE - 1; j++) {
        const int ts = t0 - (FRAME_SIZE - 1) + j;
        const long off = (long)ts * F_TOTAL + f0;
        #pragma unroll
        for (int u = 0; u < 4; u++) {
            if (ts >= 0) {
                wr[j][u] = sp[off + u];
                wi[j][u] = sp[off + spec_ch + u];
            } else {
                wr[j][u] = 0.0f;
                wi[j][u] = 0.0f;
            }
        }
    }

    const float* cf = coefs + (long)b * coef_b + (long)t0 * NUM_FREQS + f0;

    #pragma unroll
    for (int tt = 0; tt < T_STRIP; tt++) {
        const int t = t0 + tt;
        const long off = (long)t * F_TOTAL + f0;

        // load newest row into tap 4
        #pragma unroll
        for (int u = 0; u < 4; u++) {
            wr[FRAME_SIZE - 1][u] = sp[off + u];
            wi[FRAME_SIZE - 1][u] = sp[off + spec_ch + u];
        }

        float ar[4] = {0.f, 0.f, 0.f, 0.f};
        float ai[4] = {0.f, 0.f, 0.f, 0.f};

        #pragma unroll
        for (int k = 0; k < FRAME_SIZE; k++) {
            const float4 crv = *(const float4*)(cf + (long)k * coef_c);
            const float4 civ = *(const float4*)(cf + (long)(FRAME_SIZE + k) * coef_c);
            const float cr[4] = {crv.x, crv.y, crv.z, crv.w};
            const float ci[4] = {civ.x, civ.y, civ.z, civ.w};
            #pragma unroll
            for (int u = 0; u < 4; u++) {
                ar[u] = fmaf(wr[k][u], cr[u], fmaf(-wi[k][u], ci[u], ar[u]));
                ai[u] = fmaf(wi[k][u], cr[u], fmaf(wr[k][u], ci[u], ai[u]));
            }
        }

        #pragma unroll
        for (int u = 0; u < 4; u++) {
            op[off + u]           = ar[u];
            op[off + spec_ch + u] = ai[u];
        }

        // slide window
        #pragma unroll
        for (int k = 0; k < FRAME_SIZE - 1; k++) {
            #pragma unroll
            for (int u = 0; u < 4; u++) {
                wr[k][u] = wr[k + 1][u];
                wi[k][u] = wi[k + 1][u];
            }
        }

        cf += NUM_FREQS;
    }

    // ---- passthrough region: bins 256..480 for this block's 32 t-values ----
    const int tBase = blockIdx.x * T_BLK;
    const int tid = threadIdx.y * 64 + threadIdx.x;   // 0..127
    const int total = T_BLK * 2 * NPASS;              // 14400
    for (int i = tid; i < total; i += 128) {
        const int f    = i % NPASS;
        const int rest = i / NPASS;
        const int ch   = rest & 1;
        const int tt   = rest >> 1;
        const long off = (long)ch * spec_ch + (long)(tBase + tt) * F_TOTAL
                       + NUM_FREQS + f;
        op[off] = sp[off];
    }
}

extern "C" void kernel_launch(void* const* d_in, const int* in_sizes, int n_in,
                              void* d_out, int out_size)
{
    const float* spec  = (const float*)d_in[0];
    const float* coefs = (const float*)d_in[1];
    float* out = (float*)d_out;

    dim3 block(64, STRIPS_PER_BLK);
    dim3 grid(T_DIM / T_BLK, B_DIM);
    deepfilter_kernel<<<grid, block>>>(spec, coefs, out);
}

// round 5
// speedup vs baseline: 1.0903x; 1.0903x over previous
#include <cuda_runtime.h>

// DeepFilter with shared-memory time tile.
// spec:  (B=8, 2, T=4096, F=481) f32
// coefs: (B=8, 10, T=4096, 256) f32  (c[0..4]=real taps, c[5..9]=imag taps)

#define NUM_FREQS 256
#define FRAME_SIZE 5
#define T_DIM 4096
#define F_TOTAL 481
#define B_DIM 8

#define T_TILE 8
#define ROWS (T_TILE + FRAME_SIZE - 1)     // 12 spec rows per tile (incl. halo)
#define NPASS (F_TOTAL - NUM_FREQS)        // 225 passthrough bins
#define NTHREADS 256

__global__ __launch_bounds__(NTHREADS, 6)
void deepfilter_kernel(const float* __restrict__ spec,
                       const float* __restrict__ coefs,
                       float* __restrict__ out)
{
    __shared__ float sm[2][ROWS][NUM_FREQS];

    const int tid = threadIdx.x;           // 0..255
    const int f   = tid;                   // one freq bin per thread
    const int b   = blockIdx.y;
    const int t0  = blockIdx.x * T_TILE;

    const long spec_ch = (long)T_DIM * F_TOTAL;
    const long spec_b  = 2 * spec_ch;
    const long coef_c  = (long)T_DIM * NUM_FREQS;
    const long coef_b  = 2 * FRAME_SIZE * coef_c;

    const float* sp = spec + (long)b * spec_b;
    float*       op = out  + (long)b * spec_b;

    // ---- load 12 spec rows (both channels) into smem ----
    // 2*12*256 = 6144 elements, 24 per thread, coalesced.
    #pragma unroll
    for (int i = 0; i < (2 * ROWS * NUM_FREQS) / NTHREADS; i++) {
        const int idx = i * NTHREADS + tid;
        const int fl  = idx & (NUM_FREQS - 1);
        const int row = (idx >> 8) % ROWS;
        const int ch  = idx / (ROWS * NUM_FREQS);
        const int ts  = t0 - (FRAME_SIZE - 1) + row;
        float v = 0.0f;
        if (ts >= 0)
            v = sp[(long)ch * spec_ch + (long)ts * F_TOTAL + fl];
        sm[ch][row][fl] = v;
    }
    __syncthreads();

    // ---- compute T_TILE outputs for this thread's bin ----
    const float* cf0 = coefs + (long)b * coef_b + (long)t0 * NUM_FREQS + f;

    #pragma unroll
    for (int tt = 0; tt < T_TILE; tt++) {
        const int t = t0 + tt;
        const float* cf = cf0 + (long)tt * NUM_FREQS;

        float ar = 0.0f, ai = 0.0f;
        #pragma unroll
        for (int k = 0; k < FRAME_SIZE; k++) {
            const float cr = __ldg(cf + (long)k * coef_c);
            const float ci = __ldg(cf + (long)(FRAME_SIZE + k) * coef_c);
            const float sr = sm[0][tt + k][f];
            const float si = sm[1][tt + k][f];
            ar = fmaf(sr, cr, fmaf(-si, ci, ar));
            ai = fmaf(si, cr, fmaf(sr, ci, ai));
        }

        const long off = (long)t * F_TOTAL + f;
        op[off]           = ar;
        op[off + spec_ch] = ai;
    }

    // ---- passthrough region: bins 256..480 for this tile's 8 t-values ----
    const int total = T_TILE * 2 * NPASS;   // 3600
    for (int i = tid; i < total; i += NTHREADS) {
        const int fl   = i % NPASS;
        const int rest = i / NPASS;
        const int ch   = rest & 1;
        const int tt   = rest >> 1;
        const long off = (long)ch * spec_ch + (long)(t0 + tt) * F_TOTAL
                       + NUM_FREQS + fl;
        op[off] = sp[off];
    }
}

extern "C" void kernel_launch(void* const* d_in, const int* in_sizes, int n_in,
                              void* d_out, int out_size)
{
    const float* spec  = (const float*)d_in[0];
    const float* coefs = (const float*)d_in[1];
    float* out = (float*)d_out;

    dim3 grid(T_DIM / T_TILE, B_DIM);
    deepfilter_kernel<<<grid, NTHREADS>>>(spec, coefs, out);
}

// round 6
// speedup vs baseline: 1.2781x; 1.1723x over previous
#include <cuda_runtime.h>

// DeepFilter: out[b,0,t,f<256] = sum_k spec_r[t+k-4,f]*c[k] - spec_i[t+k-4,f]*c[5+k]
//             out[b,1,t,f<256] = sum_k spec_i[t+k-4,f]*c[k] + spec_r[t+k-4,f]*c[5+k]
//             out[b,:,t,f>=256] = spec[b,:,t,f]
// spec:  (B=8, 2, T=4096, F=481) f32
// coefs: (B=8, 10, T=4096, 256) f32   (c[0..4]=real taps, c[5..9]=imag taps)

#define NUM_FREQS 256
#define FRAME_SIZE 5
#define T_DIM 4096
#define F_TOTAL 481
#define B_DIM 8

__global__ __launch_bounds__(128, 12)
void deepfilter_kernel(const float* __restrict__ spec,
                       const float* __restrict__ coefs,
                       float* __restrict__ out)
{
    const int tid = threadIdx.x;
    const int t = blockIdx.x;
    const int b = blockIdx.y;

    const long spec_ch = (long)T_DIM * F_TOTAL;
    const long spec_b  = 2 * spec_ch;
    const long coef_c  = (long)T_DIM * NUM_FREQS;
    const long coef_b  = 2 * FRAME_SIZE * coef_c;

    const float* sp_base = spec + (long)b * spec_b + (long)t * F_TOTAL;
    float*       ot_base = out  + (long)b * spec_b + (long)t * F_TOTAL;

    if (tid < 64) {
        // Filtered region: 4 bins per thread, float4 coef loads (16B aligned).
        const int f0 = tid * 4;
        const float* cf = coefs + (long)b * coef_b + (long)t * NUM_FREQS + f0;

        float ar0 = 0.f, ar1 = 0.f, ar2 = 0.f, ar3 = 0.f;
        float ai0 = 0.f, ai1 = 0.f, ai2 = 0.f, ai3 = 0.f;

        #pragma unroll
        for (int k = 0; k < FRAME_SIZE; k++) {
            const int ts = t + k - (FRAME_SIZE - 1);   // lookahead = 0
            if (ts >= 0) {
                // coefs are single-use: stream them (evict-first in L2)
                const float4 cr = __ldcs((const float4*)(cf + (long)k * coef_c));
                const float4 ci = __ldcs((const float4*)(cf + (long)(FRAME_SIZE + k) * coef_c));

                const float* sr = sp_base + (long)(ts - t) * F_TOTAL + f0;
                const float* si = sr + spec_ch;

                const float sr0 = __ldg(sr + 0), sr1 = __ldg(sr + 1);
                const float sr2 = __ldg(sr + 2), sr3 = __ldg(sr + 3);
                const float si0 = __ldg(si + 0), si1 = __ldg(si + 1);
                const float si2 = __ldg(si + 2), si3 = __ldg(si + 3);

                ar0 = fmaf(sr0, cr.x, fmaf(-si0, ci.x, ar0));
                ar1 = fmaf(sr1, cr.y, fmaf(-si1, ci.y, ar1));
                ar2 = fmaf(sr2, cr.z, fmaf(-si2, ci.z, ar2));
                ar3 = fmaf(sr3, cr.w, fmaf(-si3, ci.w, ar3));

                ai0 = fmaf(si0, cr.x, fmaf(sr0, ci.x, ai0));
                ai1 = fmaf(si1, cr.y, fmaf(sr1, ci.y, ai1));
                ai2 = fmaf(si2, cr.z, fmaf(sr2, ci.z, ai2));
                ai3 = fmaf(si3, cr.w, fmaf(sr3, ci.w, ai3));
            }
        }

        float* outr = ot_base + f0;
        float* outi = outr + spec_ch;
        __stcs(outr + 0, ar0); __stcs(outr + 1, ar1);
        __stcs(outr + 2, ar2); __stcs(outr + 3, ar3);
        __stcs(outi + 0, ai0); __stcs(outi + 1, ai1);
        __stcs(outi + 2, ai2); __stcs(outi + 3, ai3);
    } else {
        // Passthrough region: bins 256..480, 4 bins per thread.
        const int f0 = NUM_FREQS + (tid - 64) * 4;
        #pragma unroll
        for (int j = 0; j < 4; j++) {
            const int f = f0 + j;
            if (f < F_TOTAL) {
                __stcs(ot_base + f,           __ldg(sp_base + f));
                __stcs(ot_base + spec_ch + f, __ldg(sp_base + spec_ch + f));
            }
        }
    }
}

extern "C" void kernel_launch(void* const* d_in, const int* in_sizes, int n_in,
                              void* d_out, int out_size)
{
    const float* spec  = (const float*)d_in[0];
    const float* coefs = (const float*)d_in[1];
    float* out = (float*)d_out;

    dim3 grid(T_DIM, B_DIM);
    deepfilter_kernel<<<grid, 128>>>(spec, coefs, out);
}